// round 1
// baseline (speedup 1.0000x reference)
#include <cuda_runtime.h>

#define BB 8
#define NN 512
#define PP 32
#define LL 3

// Scratch (device globals: no allocation in kernel_launch)
__device__ float g_t31[BB*NN*PP];        // [b][n][p]
__device__ float g_muA[BB*PP*NN];        // [b][p][n]
__device__ float g_muB[BB*PP*NN];
__device__ float g_z[2][BB*PP*NN];       // k-split partials of mu@adj

// ---------------------------------------------------------------------------
// K1: t31[b][n][p] = sum_m relu( A_p(n) + B_p*w[b,n,m] + C_p(n)*s[b,m] )
//   A_p(n) = t4[p,0]*x[n] + 0.5*t4[p,2] + t4[p,3]
//   B_p    = t4[p,1]
//   C_p(n) = -0.5*t4[p,2]*s[n],   s = 2x-1
// grid (N, B), block 256. lane = p; 8 warps split m.
// ---------------------------------------------------------------------------
__global__ __launch_bounds__(256) void edge_kernel(
    const float* __restrict__ x, const float* __restrict__ wgt,
    const float* __restrict__ t4, int layer)
{
    __shared__ float w_s[NN];
    __shared__ float s_s[NN];
    __shared__ float red[8][PP];

    int n = blockIdx.x, b = blockIdx.y;
    int tid = threadIdx.x;
    int lane = tid & 31;
    int wid  = tid >> 5;

    const float* wrow = wgt + ((size_t)(b * NN + n)) * NN;
    const float* xb   = x + b * NN;

    for (int m = tid; m < NN; m += 256) {
        w_s[m] = wrow[m];
        s_s[m] = 2.0f * xb[m] - 1.0f;
    }

    const float* t4p = t4 + (layer * PP + lane) * 4;
    float c0 = t4p[0], c1 = t4p[1], c2 = t4p[2], c3 = t4p[3];
    float xn = xb[n];
    float sn = 2.0f * xn - 1.0f;
    float A  = fmaf(c0, xn, fmaf(0.5f, c2, c3));
    float C  = -0.5f * c2 * sn;

    __syncthreads();

    float acc = 0.0f;
    int m0 = wid * (NN / 8);
    #pragma unroll 4
    for (int m = m0; m < m0 + NN / 8; m += 4) {
        float4 w4 = *(const float4*)(w_s + m);
        float4 s4 = *(const float4*)(s_s + m);
        acc += fmaxf(fmaf(C, s4.x, fmaf(c1, w4.x, A)), 0.0f);
        acc += fmaxf(fmaf(C, s4.y, fmaf(c1, w4.y, A)), 0.0f);
        acc += fmaxf(fmaf(C, s4.z, fmaf(c1, w4.z, A)), 0.0f);
        acc += fmaxf(fmaf(C, s4.w, fmaf(c1, w4.w, A)), 0.0f);
    }

    red[wid][lane] = acc;
    __syncthreads();
    if (wid == 0) {
        float s = red[0][lane];
        #pragma unroll
        for (int k = 1; k < 8; k++) s += red[k][lane];
        g_t31[(b * NN + n) * PP + lane] = s;
    }
}

// ---------------------------------------------------------------------------
// K2: z[ks][b][q][j] = sum_{n in split ks} mu_in[b][q][n] * adj[b][n][j]
// grid (N/32, B, 2), block 256. thread: j = jt*32 + lane, qg = wid handles 4 q.
// ---------------------------------------------------------------------------
__global__ __launch_bounds__(256) void zpart_kernel(
    const float* __restrict__ adj, int mu_sel)
{
    __shared__ float mu_s[PP][64];

    int jt = blockIdx.x, b = blockIdx.y, ks = blockIdx.z;
    int tid = threadIdx.x;
    int lane = tid & 31;
    int qg = tid >> 5;   // 0..7
    int j = jt * 32 + lane;

    const float* mu_in = (mu_sel == 0) ? g_muA : g_muB;

    float acc0 = 0.f, acc1 = 0.f, acc2 = 0.f, acc3 = 0.f;
    int nbase = ks * (NN / 2);

    for (int nc = 0; nc < NN / 2; nc += 64) {
        __syncthreads();
        for (int idx = tid; idx < PP * 64; idx += 256) {
            int q = idx >> 6, nn = idx & 63;
            mu_s[q][nn] = mu_in[(b * PP + q) * NN + nbase + nc + nn];
        }
        __syncthreads();
        #pragma unroll 8
        for (int nn = 0; nn < 64; nn++) {
            float a = adj[((size_t)(b * NN + nbase + nc + nn)) * NN + j];
            acc0 = fmaf(mu_s[qg * 4 + 0][nn], a, acc0);
            acc1 = fmaf(mu_s[qg * 4 + 1][nn], a, acc1);
            acc2 = fmaf(mu_s[qg * 4 + 2][nn], a, acc2);
            acc3 = fmaf(mu_s[qg * 4 + 3][nn], a, acc3);
        }
    }

    float* zo = g_z[ks] + ((size_t)(b * PP + qg * 4)) * NN + j;
    zo[0 * NN] = acc0;
    zo[1 * NN] = acc1;
    zo[2 * NN] = acc2;
    zo[3 * NN] = acc3;
}

// ---------------------------------------------------------------------------
// K3: mu_out[b][p][j] = relu( term1[p,j] + sum_q t2[p,q]*z[q,j]
//                                         + sum_q t3[p,q]*t31[q,j] )
// grid (N/32, B), block 256. thread: j = jt*32 + lane, pg = wid handles 4 p.
// dst: 0 -> g_muA, 1 -> g_muB, 2 -> d_out
// ---------------------------------------------------------------------------
__global__ __launch_bounds__(256) void epilogue_kernel(
    const float* __restrict__ x, const float* __restrict__ extra,
    const float* __restrict__ t1, const float* __restrict__ t2,
    const float* __restrict__ t3, int layer, int has_z,
    int dst, float* __restrict__ out)
{
    __shared__ float z_s[PP][33];
    __shared__ float t31_s[PP][33];
    __shared__ float t2_s[PP][PP];
    __shared__ float t3_s[PP][PP];

    int jt = blockIdx.x, b = blockIdx.y;
    int tid = threadIdx.x;
    int lane = tid & 31;
    int pg = tid >> 5;
    int j = jt * 32 + lane;

    for (int idx = tid; idx < PP * PP; idx += 256) {
        t2_s[idx >> 5][idx & 31] = t2[layer * PP * PP + idx];
        t3_s[idx >> 5][idx & 31] = t3[layer * PP * PP + idx];
    }
    // t31 global layout [b][n][p] -> shared [q][jj]
    for (int idx = tid; idx < PP * 32; idx += 256) {
        int jj = idx >> 5, q = idx & 31;
        t31_s[q][jj] = g_t31[(b * NN + jt * 32 + jj) * PP + q];
    }
    if (has_z) {
        for (int idx = tid; idx < PP * 32; idx += 256) {
            int q = idx >> 5, jj = idx & 31;
            size_t base = (size_t)(b * PP + q) * NN + jt * 32 + jj;
            z_s[q][jj] = g_z[0][base] + g_z[1][base];
        }
    } else {
        for (int idx = tid; idx < PP * 32; idx += 256)
            z_s[idx >> 5][idx & 31] = 0.0f;
    }
    __syncthreads();

    float xv = x[b * NN + j];
    float ev = extra[b * NN + j];

    float o[4];
    const float* t1b = t1 + (layer * PP + pg * 4) * 3;
    #pragma unroll
    for (int k = 0; k < 4; k++)
        o[k] = fmaf(t1b[k * 3 + 0], 1.0f - xv,
                    fmaf(t1b[k * 3 + 2], ev, t1b[k * 3 + 1]));

    #pragma unroll
    for (int q = 0; q < PP; q++) {
        float zq = z_s[q][lane];
        float tq = t31_s[q][lane];
        #pragma unroll
        for (int k = 0; k < 4; k++) {
            o[k] = fmaf(t2_s[pg * 4 + k][q], zq, o[k]);
            o[k] = fmaf(t3_s[pg * 4 + k][q], tq, o[k]);
        }
    }

    float* mo_base = (dst == 0) ? g_muA : (dst == 1) ? g_muB : out;
    float* mo = mo_base + (size_t)(b * PP + pg * 4) * NN + j;
    #pragma unroll
    for (int k = 0; k < 4; k++)
        mo[k * NN] = fmaxf(o[k], 0.0f);
}

// ---------------------------------------------------------------------------
extern "C" void kernel_launch(void* const* d_in, const int* in_sizes, int n_in,
                              void* d_out, int out_size)
{
    const float* x     = (const float*)d_in[0];
    const float* adj   = (const float*)d_in[1];
    const float* wgt   = (const float*)d_in[2];
    const float* extra = (const float*)d_in[3];
    const float* t1    = (const float*)d_in[4];
    const float* t2    = (const float*)d_in[5];
    const float* t3    = (const float*)d_in[6];
    const float* t4    = (const float*)d_in[7];
    float* out = (float*)d_out;

    dim3 edge_grid(NN, BB);
    dim3 z_grid(NN / 32, BB, 2);
    dim3 epi_grid(NN / 32, BB);

    // layer 0: mu_prev = 0 -> no z term. writes g_muA (dst=0)
    edge_kernel<<<edge_grid, 256>>>(x, wgt, t4, 0);
    epilogue_kernel<<<epi_grid, 256>>>(x, extra, t1, t2, t3, 0, 0, 0, out);

    // layer 1: reads g_muA (sel=0), writes g_muB (dst=1)
    edge_kernel<<<edge_grid, 256>>>(x, wgt, t4, 1);
    zpart_kernel<<<z_grid, 256>>>(adj, 0);
    epilogue_kernel<<<epi_grid, 256>>>(x, extra, t1, t2, t3, 1, 1, 1, out);

    // layer 2: reads g_muB (sel=1), writes d_out (dst=2)
    edge_kernel<<<edge_grid, 256>>>(x, wgt, t4, 2);
    zpart_kernel<<<z_grid, 256>>>(adj, 1);
    epilogue_kernel<<<epi_grid, 256>>>(x, extra, t1, t2, t3, 2, 1, 2, out);
}

// round 2
// speedup vs baseline: 1.3196x; 1.3196x over previous
#include <cuda_runtime.h>

#define BB 8
#define NN 512
#define PP 32
#define LL 3
#define KS 16          // n-splits for zpart

typedef unsigned long long ull;

// Scratch (device globals: no allocation in kernel_launch)
__device__ float g_t31[BB*NN*PP];          // [b][n][p]
__device__ float g_muA[BB*PP*NN];          // [b][p][n]
__device__ float g_muB[BB*PP*NN];
__device__ float g_z[KS][BB*PP*NN];        // k-split partials of mu@adj

// ---- packed f32x2 helpers (sm_100+) ---------------------------------------
__device__ __forceinline__ ull pk(float lo, float hi) {
    ull r; asm("mov.b64 %0,{%1,%2};" : "=l"(r) : "f"(lo), "f"(hi)); return r;
}
__device__ __forceinline__ void upk(ull v, float& lo, float& hi) {
    asm("mov.b64 {%0,%1},%2;" : "=f"(lo), "=f"(hi) : "l"(v));
}
__device__ __forceinline__ ull fma2(ull a, ull b, ull c) {
    ull d; asm("fma.rn.f32x2 %0,%1,%2,%3;" : "=l"(d) : "l"(a), "l"(b), "l"(c));
    return d;
}

// ---------------------------------------------------------------------------
// K1: t31[b][n][p] = sum_m relu( A_p(n) + B_p*w[b,n,m] + C_p(n)*s[b,m] )
//   A = t4[p,0]*x[n] + 0.5*t4[p,2] + t4[p,3];  B = t4[p,1];
//   C = -0.5*t4[p,2]*s[n];  s = 2x-1
// grid (N, B), block 256. lane = p; 8 warps split m. Packed f32x2 FMAs.
// ---------------------------------------------------------------------------
__global__ __launch_bounds__(256) void edge_kernel(
    const float* __restrict__ x, const float* __restrict__ wgt,
    const float* __restrict__ t4, int layer)
{
    __shared__ float w_s[NN];
    __shared__ float s_s[NN];
    __shared__ float red[8][PP];

    int n = blockIdx.x, b = blockIdx.y;
    int tid = threadIdx.x;
    int lane = tid & 31;
    int wid  = tid >> 5;

    const float* wrow = wgt + ((size_t)(b * NN + n)) * NN;
    const float* xb   = x + b * NN;

    for (int m = tid; m < NN; m += 256) {
        w_s[m] = wrow[m];
        s_s[m] = 2.0f * xb[m] - 1.0f;
    }

    const float* t4p = t4 + (layer * PP + lane) * 4;
    float c0 = t4p[0], c1 = t4p[1], c2 = t4p[2], c3 = t4p[3];
    float xn = xb[n];
    float sn = 2.0f * xn - 1.0f;
    float A  = fmaf(c0, xn, fmaf(0.5f, c2, c3));
    float C  = -0.5f * c2 * sn;

    ull A2 = pk(A, A);
    ull B2 = pk(c1, c1);
    ull C2 = pk(C, C);

    __syncthreads();

    float acc0 = 0.0f, acc1 = 0.0f;
    int m0 = wid * (NN / 8);
    #pragma unroll 4
    for (int m = m0; m < m0 + NN / 8; m += 4) {
        float4 w4 = *(const float4*)(w_s + m);
        float4 s4 = *(const float4*)(s_s + m);
        ull v0 = fma2(C2, pk(s4.x, s4.y), fma2(B2, pk(w4.x, w4.y), A2));
        ull v1 = fma2(C2, pk(s4.z, s4.w), fma2(B2, pk(w4.z, w4.w), A2));
        float a, bb;
        upk(v0, a, bb);
        acc0 += fmaxf(a, 0.0f);
        acc1 += fmaxf(bb, 0.0f);
        upk(v1, a, bb);
        acc0 += fmaxf(a, 0.0f);
        acc1 += fmaxf(bb, 0.0f);
    }

    red[wid][lane] = acc0 + acc1;
    __syncthreads();
    if (wid == 0) {
        float s = red[0][lane];
        #pragma unroll
        for (int k = 1; k < 8; k++) s += red[k][lane];
        g_t31[(b * NN + n) * PP + lane] = s;
    }
}

// ---------------------------------------------------------------------------
// K2: z[ks][b][q][j] = sum_{n in 32-slice ks} mu_in[b][q][n] * adj[b][n][j]
// grid (4, B, KS), block 256.
//   warp w: qo = w&3 (8 q's), nh = w>>2 (16-row n half)
//   lane: j = blockIdx.x*128 + lane*4   (float4 of adj per iter)
// mu staged to shared transposed once; inner loop: 1 LDG.128 + 2 LDS.128 + 32 FFMA.
// ---------------------------------------------------------------------------
__global__ __launch_bounds__(256) void zpart_kernel(
    const float* __restrict__ adj, int mu_sel)
{
    __shared__ float mu_s[32][36];   // [nn][q], pad 36 keeps 16B alignment

    int jt = blockIdx.x, b = blockIdx.y, ks = blockIdx.z;
    int tid  = threadIdx.x;
    int lane = tid & 31;
    int wid  = tid >> 5;
    int qo   = wid & 3;        // q octet: q = qo*8 .. qo*8+7
    int nh   = wid >> 2;       // 0/1: n half
    int n0   = ks * 32;
    int j    = jt * 128 + lane * 4;

    const float* mu_in = (mu_sel == 0) ? g_muA : g_muB;

    // stage mu[b][q][n0..n0+32) transposed -> mu_s[nn][q]
    {
        int q  = tid >> 3;           // 0..31
        int ni = (tid & 7) * 4;      // 0..28
        float4 v = *(const float4*)(mu_in + (b * PP + q) * NN + n0 + ni);
        mu_s[ni + 0][q] = v.x;
        mu_s[ni + 1][q] = v.y;
        mu_s[ni + 2][q] = v.z;
        mu_s[ni + 3][q] = v.w;
    }
    __syncthreads();

    float4 acc[8];
    #pragma unroll
    for (int i = 0; i < 8; i++) acc[i] = make_float4(0.f, 0.f, 0.f, 0.f);

    const float* arow = adj + ((size_t)(b * NN + n0 + nh * 16)) * NN + j;

    #pragma unroll 4
    for (int nn = 0; nn < 16; nn++) {
        float4 a4 = *(const float4*)(arow + (size_t)nn * NN);
        int nr = nh * 16 + nn;
        float4 m0 = *(const float4*)&mu_s[nr][qo * 8];
        float4 m1 = *(const float4*)&mu_s[nr][qo * 8 + 4];
        const float mq[8] = {m0.x, m0.y, m0.z, m0.w, m1.x, m1.y, m1.z, m1.w};
        #pragma unroll
        for (int i = 0; i < 8; i++) {
            acc[i].x = fmaf(mq[i], a4.x, acc[i].x);
            acc[i].y = fmaf(mq[i], a4.y, acc[i].y);
            acc[i].z = fmaf(mq[i], a4.z, acc[i].z);
            acc[i].w = fmaf(mq[i], a4.w, acc[i].w);
        }
    }

    // nh halves write to the same location -> keep them separate: use atomic-free
    // trick: the two n-halves are accumulated by DIFFERENT warps, so give each
    // half its own ks slot? No: fold via shared. Simpler: each (ks) block covers
    // 32 n; halves must be summed. Sum via shared exchange:
    __shared__ float half_s[2][8][32][4];  // [nh][qo][lane][jj] for one q at a time
    float* gz = g_z[ks] + ((size_t)(b * PP + qo * 8)) * NN + j;
    #pragma unroll
    for (int i = 0; i < 8; i++) {
        half_s[nh][qo][lane][0] = acc[i].x;
        half_s[nh][qo][lane][1] = acc[i].y;
        half_s[nh][qo][lane][2] = acc[i].z;
        half_s[nh][qo][lane][3] = acc[i].w;
        __syncthreads();
        if (nh == 0) {
            float4 r;
            r.x = acc[i].x + half_s[1][qo][lane][0];
            r.y = acc[i].y + half_s[1][qo][lane][1];
            r.z = acc[i].z + half_s[1][qo][lane][2];
            r.w = acc[i].w + half_s[1][qo][lane][3];
            *(float4*)(gz + (size_t)i * NN) = r;
        }
        __syncthreads();
    }
}

// ---------------------------------------------------------------------------
// K3: mu_out[b][p][j] = relu( term1 + sum_q t2[p,q]*z[q,j] + sum_q t3[p,q]*t31[q,j] )
// grid (N/32, B), block 256. j = jt*32 + lane, pg = wid handles 4 p.
// dst: 0 -> g_muA, 1 -> g_muB, 2 -> d_out
// ---------------------------------------------------------------------------
__global__ __launch_bounds__(256) void epilogue_kernel(
    const float* __restrict__ x, const float* __restrict__ extra,
    const float* __restrict__ t1, const float* __restrict__ t2,
    const float* __restrict__ t3, int layer, int has_z,
    int dst, float* __restrict__ out)
{
    __shared__ float z_s[PP][33];
    __shared__ float t31_s[PP][33];
    __shared__ float t2_s[PP][PP];
    __shared__ float t3_s[PP][PP];

    int jt = blockIdx.x, b = blockIdx.y;
    int tid = threadIdx.x;
    int lane = tid & 31;
    int pg = tid >> 5;
    int j = jt * 32 + lane;

    for (int idx = tid; idx < PP * PP; idx += 256) {
        t2_s[idx >> 5][idx & 31] = t2[layer * PP * PP + idx];
        t3_s[idx >> 5][idx & 31] = t3[layer * PP * PP + idx];
    }
    for (int idx = tid; idx < PP * 32; idx += 256) {
        int jj = idx >> 5, q = idx & 31;
        t31_s[q][jj] = g_t31[(b * NN + jt * 32 + jj) * PP + q];
    }
    for (int idx = tid; idx < PP * 32; idx += 256) {
        int q = idx >> 5, jj = idx & 31;
        float s = 0.0f;
        if (has_z) {
            size_t base = (size_t)(b * PP + q) * NN + jt * 32 + jj;
            #pragma unroll
            for (int ks = 0; ks < KS; ks++) s += g_z[ks][base];
        }
        z_s[q][jj] = s;
    }
    __syncthreads();

    float xv = x[b * NN + j];
    float ev = extra[b * NN + j];

    float o[4];
    const float* t1b = t1 + (layer * PP + pg * 4) * 3;
    #pragma unroll
    for (int k = 0; k < 4; k++)
        o[k] = fmaf(t1b[k * 3 + 0], 1.0f - xv,
                    fmaf(t1b[k * 3 + 2], ev, t1b[k * 3 + 1]));

    #pragma unroll
    for (int q = 0; q < PP; q++) {
        float zq = z_s[q][lane];
        float tq = t31_s[q][lane];
        #pragma unroll
        for (int k = 0; k < 4; k++) {
            o[k] = fmaf(t2_s[pg * 4 + k][q], zq, o[k]);
            o[k] = fmaf(t3_s[pg * 4 + k][q], tq, o[k]);
        }
    }

    float* mo_base = (dst == 0) ? g_muA : (dst == 1) ? g_muB : out;
    float* mo = mo_base + (size_t)(b * PP + pg * 4) * NN + j;
    #pragma unroll
    for (int k = 0; k < 4; k++)
        mo[k * NN] = fmaxf(o[k], 0.0f);
}

// ---------------------------------------------------------------------------
extern "C" void kernel_launch(void* const* d_in, const int* in_sizes, int n_in,
                              void* d_out, int out_size)
{
    const float* x     = (const float*)d_in[0];
    const float* adj   = (const float*)d_in[1];
    const float* wgt   = (const float*)d_in[2];
    const float* extra = (const float*)d_in[3];
    const float* t1    = (const float*)d_in[4];
    const float* t2    = (const float*)d_in[5];
    const float* t3    = (const float*)d_in[6];
    const float* t4    = (const float*)d_in[7];
    float* out = (float*)d_out;

    dim3 edge_grid(NN, BB);
    dim3 z_grid(4, BB, KS);
    dim3 epi_grid(NN / 32, BB);

    // layer 0: mu_prev = 0 -> no z term. writes g_muA (dst=0)
    edge_kernel<<<edge_grid, 256>>>(x, wgt, t4, 0);
    epilogue_kernel<<<epi_grid, 256>>>(x, extra, t1, t2, t3, 0, 0, 0, out);

    // layer 1: reads g_muA (sel=0), writes g_muB (dst=1)
    edge_kernel<<<edge_grid, 256>>>(x, wgt, t4, 1);
    zpart_kernel<<<z_grid, 256>>>(adj, 0);
    epilogue_kernel<<<epi_grid, 256>>>(x, extra, t1, t2, t3, 1, 1, 1, out);

    // layer 2: reads g_muB (sel=1), writes d_out (dst=2)
    edge_kernel<<<edge_grid, 256>>>(x, wgt, t4, 2);
    zpart_kernel<<<z_grid, 256>>>(adj, 1);
    epilogue_kernel<<<epi_grid, 256>>>(x, extra, t1, t2, t3, 2, 1, 2, out);
}

// round 3
// speedup vs baseline: 1.5811x; 1.1981x over previous
#include <cuda_runtime.h>

#define BB 8
#define NN 512
#define PP 32
#define LL 3
#define KS 8           // n-splits for zpart (n-chunk = 64)

typedef unsigned long long ull;

// Scratch (device globals: no allocation in kernel_launch)
__device__ float g_t31[LL][BB*NN*PP];      // [l][b][n][p]
__device__ float g_muA[BB*PP*NN];          // [b][p][n]
__device__ float g_muB[BB*PP*NN];
__device__ float g_z[KS][BB*PP*NN];        // k-split partials of mu@adj

// ---- packed f32x2 helpers (sm_100+) ---------------------------------------
__device__ __forceinline__ ull pk(float lo, float hi) {
    ull r; asm("mov.b64 %0,{%1,%2};" : "=l"(r) : "f"(lo), "f"(hi)); return r;
}
__device__ __forceinline__ void upk(ull v, float& lo, float& hi) {
    asm("mov.b64 {%0,%1},%2;" : "=f"(lo), "=f"(hi) : "l"(v));
}
__device__ __forceinline__ ull fma2(ull a, ull b, ull c) {
    ull d; asm("fma.rn.f32x2 %0,%1,%2,%3;" : "=l"(d) : "l"(a), "l"(b), "l"(c));
    return d;
}

union F4U2 { float4 f4; ull u2[2]; };

// ---- cp.async helpers ------------------------------------------------------
__device__ __forceinline__ void cp16(unsigned smem_dst, const void* gsrc) {
    asm volatile("cp.async.ca.shared.global [%0], [%1], 16;"
                 :: "r"(smem_dst), "l"(gsrc));
}
__device__ __forceinline__ void cp_commit() {
    asm volatile("cp.async.commit_group;");
}
template <int N>
__device__ __forceinline__ void cp_wait() {
    asm volatile("cp.async.wait_group %0;" :: "n"(N));
}

// ---------------------------------------------------------------------------
// K1 (fused over layers):
//   t31[l][b][n][p] = sum_m relu( A + B*w[b,n,m] + C*s[b,m] )
//   A = t4[l,p,0]*x[n] + 0.5*t4[l,p,2] + t4[l,p,3];  B = t4[l,p,1];
//   C = -0.5*t4[l,p,2]*s[n];  s = 2x-1
// grid (N, B), block 256. lane = p; 8 warps split m; 3 layers interleaved.
// ---------------------------------------------------------------------------
__global__ __launch_bounds__(256) void edge_kernel(
    const float* __restrict__ x, const float* __restrict__ wgt,
    const float* __restrict__ t4)
{
    __shared__ float w_s[NN];
    __shared__ float s_s[NN];
    __shared__ float red_s[LL][8][PP];

    int n = blockIdx.x, b = blockIdx.y;
    int tid = threadIdx.x;
    int lane = tid & 31;
    int wid  = tid >> 5;

    const float* wrow = wgt + ((size_t)(b * NN + n)) * NN;
    const float* xb   = x + b * NN;

    for (int m = tid; m < NN; m += 256) {
        w_s[m] = wrow[m];
        s_s[m] = 2.0f * xb[m] - 1.0f;
    }

    float xn = xb[n];
    float sn = 2.0f * xn - 1.0f;

    ull A2[LL], B2[LL], C2[LL];
    #pragma unroll
    for (int l = 0; l < LL; l++) {
        const float* t4p = t4 + (l * PP + lane) * 4;
        float c0 = t4p[0], c1 = t4p[1], c2 = t4p[2], c3 = t4p[3];
        float A  = fmaf(c0, xn, fmaf(0.5f, c2, c3));
        float C  = -0.5f * c2 * sn;
        A2[l] = pk(A, A);
        B2[l] = pk(c1, c1);
        C2[l] = pk(C, C);
    }

    __syncthreads();

    float acc0[LL] = {0.f, 0.f, 0.f};
    float acc1[LL] = {0.f, 0.f, 0.f};

    int m0 = wid * (NN / 8);
    #pragma unroll 4
    for (int m = m0; m < m0 + NN / 8; m += 4) {
        F4U2 w4, s4;
        w4.f4 = *(const float4*)(w_s + m);
        s4.f4 = *(const float4*)(s_s + m);
        #pragma unroll
        for (int l = 0; l < LL; l++) {
            ull v0 = fma2(C2[l], s4.u2[0], fma2(B2[l], w4.u2[0], A2[l]));
            ull v1 = fma2(C2[l], s4.u2[1], fma2(B2[l], w4.u2[1], A2[l]));
            float a, bb;
            upk(v0, a, bb);
            acc0[l] += fmaxf(a, 0.0f);
            acc1[l] += fmaxf(bb, 0.0f);
            upk(v1, a, bb);
            acc0[l] += fmaxf(a, 0.0f);
            acc1[l] += fmaxf(bb, 0.0f);
        }
    }

    #pragma unroll
    for (int l = 0; l < LL; l++)
        red_s[l][wid][lane] = acc0[l] + acc1[l];
    __syncthreads();

    if (wid < LL) {
        float s = red_s[wid][0][lane];
        #pragma unroll
        for (int k = 1; k < 8; k++) s += red_s[wid][k][lane];
        g_t31[wid][(b * NN + n) * PP + lane] = s;
    }
}

// ---------------------------------------------------------------------------
// K2: z[ks][b][q][j] = sum_{n in 64-chunk ks} mu_in[b][q][n] * adj[b][n][j]
// grid (4, B, KS), block 256.
//   adj staged in shared (16n x 128j tiles, cp.async double-buffered)
//   warp w owns q-quad q = 4w..4w+3; lane owns j = jt*128 + lane*4.
//   No cross-warp reduction.
// ---------------------------------------------------------------------------
__global__ __launch_bounds__(256) void zpart_kernel(
    const float* __restrict__ adj, int mu_sel)
{
    __shared__ float a_s[2][16][128];
    __shared__ float mu_s[64][PP];    // [nn][q]

    int jt = blockIdx.x, b = blockIdx.y, ks = blockIdx.z;
    int tid  = threadIdx.x;
    int lane = tid & 31;
    int wid  = tid >> 5;
    int n0   = ks * 64;
    int j0   = jt * 128;

    const float* mu_in = (mu_sel == 0) ? g_muA : g_muB;

    // stage mu[b][q][n0..n0+64) transposed -> mu_s[nn][q] (coalesced over n)
    {
        int q   = tid >> 4;          // 0..15 (two passes below cover 32 q? no:)
        // 256 threads, need 32 q x 16 chunks: q = tid >> 4 gives 0..15 only.
        // Do two iterations: i in {tid, tid+256} -> covers 512 float4 loads.
        #pragma unroll
        for (int pass = 0; pass < 2; pass++) {
            int i   = tid + pass * 256;     // 0..511
            int qq  = i >> 4;               // 0..31
            int nn4 = (i & 15) * 4;         // 0..60
            float4 v = *(const float4*)(mu_in + (b * PP + qq) * NN + n0 + nn4);
            mu_s[nn4 + 0][qq] = v.x;
            mu_s[nn4 + 1][qq] = v.y;
            mu_s[nn4 + 2][qq] = v.z;
            mu_s[nn4 + 3][qq] = v.w;
        }
        (void)q;
    }

    // stage adj tile t into buffer buf: rows n0+t*16 .. +16, cols j0..j0+128
    auto stage = [&](int t, int buf) {
        #pragma unroll
        for (int pass = 0; pass < 2; pass++) {
            int i    = tid + pass * 256;    // 0..511
            int row  = i >> 5;              // 0..15
            int col4 = (i & 31) * 4;        // 0..124
            const float* src =
                adj + ((size_t)(b * NN + n0 + t * 16 + row)) * NN + j0 + col4;
            unsigned dst = (unsigned)__cvta_generic_to_shared(&a_s[buf][row][col4]);
            cp16(dst, src);
        }
        cp_commit();
    };

    stage(0, 0);

    float4 acc[4];
    #pragma unroll
    for (int i = 0; i < 4; i++) acc[i] = make_float4(0.f, 0.f, 0.f, 0.f);

    #pragma unroll
    for (int t = 0; t < 4; t++) {
        if (t + 1 < 4) { stage(t + 1, (t + 1) & 1); cp_wait<1>(); }
        else            cp_wait<0>();
        __syncthreads();

        int buf = t & 1;
        #pragma unroll
        for (int nn = 0; nn < 16; nn++) {
            float4 a4 = *(const float4*)&a_s[buf][nn][lane * 4];
            float4 m4 = *(const float4*)&mu_s[t * 16 + nn][wid * 4];
            acc[0].x = fmaf(m4.x, a4.x, acc[0].x);
            acc[0].y = fmaf(m4.x, a4.y, acc[0].y);
            acc[0].z = fmaf(m4.x, a4.z, acc[0].z);
            acc[0].w = fmaf(m4.x, a4.w, acc[0].w);
            acc[1].x = fmaf(m4.y, a4.x, acc[1].x);
            acc[1].y = fmaf(m4.y, a4.y, acc[1].y);
            acc[1].z = fmaf(m4.y, a4.z, acc[1].z);
            acc[1].w = fmaf(m4.y, a4.w, acc[1].w);
            acc[2].x = fmaf(m4.z, a4.x, acc[2].x);
            acc[2].y = fmaf(m4.z, a4.y, acc[2].y);
            acc[2].z = fmaf(m4.z, a4.z, acc[2].z);
            acc[2].w = fmaf(m4.z, a4.w, acc[2].w);
            acc[3].x = fmaf(m4.w, a4.x, acc[3].x);
            acc[3].y = fmaf(m4.w, a4.y, acc[3].y);
            acc[3].z = fmaf(m4.w, a4.z, acc[3].z);
            acc[3].w = fmaf(m4.w, a4.w, acc[3].w);
        }
        __syncthreads();
    }

    float* gz = g_z[ks] + ((size_t)(b * PP + wid * 4)) * NN + j0 + lane * 4;
    #pragma unroll
    for (int i = 0; i < 4; i++)
        *(float4*)(gz + (size_t)i * NN) = acc[i];
}

// ---------------------------------------------------------------------------
// K3: mu_out[b][p][j] = relu( term1 + sum_q t2[p,q]*z[q,j] + sum_q t3[p,q]*t31[q,j] )
// grid (N/32, B), block 256. j = jt*32 + lane, pg = wid handles 4 p.
// dst: 0 -> g_muA, 1 -> g_muB, 2 -> d_out
// ---------------------------------------------------------------------------
__global__ __launch_bounds__(256) void epilogue_kernel(
    const float* __restrict__ x, const float* __restrict__ extra,
    const float* __restrict__ t1, const float* __restrict__ t2,
    const float* __restrict__ t3, int layer, int has_z,
    int dst, float* __restrict__ out)
{
    __shared__ float z_s[PP][33];
    __shared__ float t31_s[PP][33];
    __shared__ float t2_s[PP][PP];
    __shared__ float t3_s[PP][PP];

    int jt = blockIdx.x, b = blockIdx.y;
    int tid = threadIdx.x;
    int lane = tid & 31;
    int pg = tid >> 5;
    int j = jt * 32 + lane;

    for (int idx = tid; idx < PP * PP; idx += 256) {
        t2_s[idx >> 5][idx & 31] = t2[layer * PP * PP + idx];
        t3_s[idx >> 5][idx & 31] = t3[layer * PP * PP + idx];
    }
    for (int idx = tid; idx < PP * 32; idx += 256) {
        int jj = idx >> 5, q = idx & 31;
        t31_s[q][jj] = g_t31[layer][(b * NN + jt * 32 + jj) * PP + q];
    }
    for (int idx = tid; idx < PP * 32; idx += 256) {
        int q = idx >> 5, jj = idx & 31;
        float s = 0.0f;
        if (has_z) {
            size_t base = (size_t)(b * PP + q) * NN + jt * 32 + jj;
            #pragma unroll
            for (int ks = 0; ks < KS; ks++) s += g_z[ks][base];
        }
        z_s[q][jj] = s;
    }
    __syncthreads();

    float xv = x[b * NN + j];
    float ev = extra[b * NN + j];

    float o[4];
    const float* t1b = t1 + (layer * PP + pg * 4) * 3;
    #pragma unroll
    for (int k = 0; k < 4; k++)
        o[k] = fmaf(t1b[k * 3 + 0], 1.0f - xv,
                    fmaf(t1b[k * 3 + 2], ev, t1b[k * 3 + 1]));

    #pragma unroll
    for (int q = 0; q < PP; q++) {
        float zq = z_s[q][lane];
        float tq = t31_s[q][lane];
        #pragma unroll
        for (int k = 0; k < 4; k++) {
            o[k] = fmaf(t2_s[pg * 4 + k][q], zq, o[k]);
            o[k] = fmaf(t3_s[pg * 4 + k][q], tq, o[k]);
        }
    }

    float* mo_base = (dst == 0) ? g_muA : (dst == 1) ? g_muB : out;
    float* mo = mo_base + (size_t)(b * PP + pg * 4) * NN + j;
    #pragma unroll
    for (int k = 0; k < 4; k++)
        mo[k * NN] = fmaxf(o[k], 0.0f);
}

// ---------------------------------------------------------------------------
extern "C" void kernel_launch(void* const* d_in, const int* in_sizes, int n_in,
                              void* d_out, int out_size)
{
    const float* x     = (const float*)d_in[0];
    const float* adj   = (const float*)d_in[1];
    const float* wgt   = (const float*)d_in[2];
    const float* extra = (const float*)d_in[3];
    const float* t1    = (const float*)d_in[4];
    const float* t2    = (const float*)d_in[5];
    const float* t3    = (const float*)d_in[6];
    const float* t4    = (const float*)d_in[7];
    float* out = (float*)d_out;

    dim3 edge_grid(NN, BB);
    dim3 z_grid(4, BB, KS);
    dim3 epi_grid(NN / 32, BB);

    // all 3 layers' t31 in one fused launch
    edge_kernel<<<edge_grid, 256>>>(x, wgt, t4);

    // layer 0: mu_prev = 0 -> no z term. writes g_muA (dst=0)
    epilogue_kernel<<<epi_grid, 256>>>(x, extra, t1, t2, t3, 0, 0, 0, out);

    // layer 1: reads g_muA (sel=0), writes g_muB (dst=1)
    zpart_kernel<<<z_grid, 256>>>(adj, 0);
    epilogue_kernel<<<epi_grid, 256>>>(x, extra, t1, t2, t3, 1, 1, 1, out);

    // layer 2: reads g_muB (sel=1), writes d_out (dst=2)
    zpart_kernel<<<z_grid, 256>>>(adj, 1);
    epilogue_kernel<<<epi_grid, 256>>>(x, extra, t1, t2, t3, 2, 1, 2, out);
}